// round 4
// baseline (speedup 1.0000x reference)
#include <cuda_runtime.h>

#define SEL   2
#define Bb    2
#define Cc    256
#define Nn    2304
#define Gg    8
#define CGd   16
#define INTER 128
#define EPSf  1e-5f
#define LOG2E 1.4426950408889634f

// ---------------- packed f32x2 helpers ----------------
typedef unsigned long long f2;

__device__ __forceinline__ f2 pack2(float lo, float hi) {
    f2 r; asm("mov.b64 %0,{%1,%2};" : "=l"(r) : "f"(lo), "f"(hi)); return r;
}
__device__ __forceinline__ f2 dup2(float v) {
    f2 r; asm("mov.b64 %0,{%1,%1};" : "=l"(r) : "f"(v)); return r;
}
__device__ __forceinline__ void unpack2(f2 v, float& lo, float& hi) {
    asm("mov.b64 {%0,%1},%2;" : "=f"(lo), "=f"(hi) : "l"(v));
}
__device__ __forceinline__ f2 fma2(f2 a, f2 b, f2 c) {
    f2 d; asm("fma.rn.f32x2 %0,%1,%2,%3;" : "=l"(d) : "l"(a), "l"(b), "l"(c)); return d;
}
__device__ __forceinline__ f2 add2(f2 a, f2 b) {
    f2 d; asm("add.rn.f32x2 %0,%1,%2;" : "=l"(d) : "l"(a), "l"(b)); return d;
}
__device__ __forceinline__ f2 mul2(f2 a, f2 b) {
    f2 d; asm("mul.rn.f32x2 %0,%1,%2;" : "=l"(d) : "l"(a), "l"(b)); return d;
}

struct __align__(16) F4 { f2 a, b; };

// ---------------- scratch ----------------
__device__ float g_theta[SEL*Bb*Gg*CGd*Nn];   // pre-scaled by log2e, [bg][d][n]
__device__ float g_phiT [SEL*Bb*Gg*CGd*Nn];
__device__ float g_gx   [SEL*Bb*Gg*CGd*Nn];
__device__ float g_outc [SEL*Bb*INTER*Nn];
__device__ float g_wy   [SEL*Bb*Cc*Nn];
__device__ float g_mean [SEL*Cc];
__device__ float g_rstd [SEL*Cc];

// ---------------- Kernel 1: grouped projections ----------------
struct ProjArgs {
    const float* x[2];
    const float* tw[2]; const float* tb[2];
    const float* pw[2]; const float* pb[2];
    const float* gw[2]; const float* gb[2];
};

__global__ __launch_bounds__(128) void proj_kernel(ProjArgs A)
{
    int tid = threadIdx.x;
    int n0  = blockIdx.x * 256;
    int g   = blockIdx.y;
    int sb  = blockIdx.z;
    int sel = sb >> 1, b = sb & 1;

    const float* tw = A.tw[sel]; const float* pw = A.pw[sel]; const float* gw = A.gw[sel];

    __shared__ __align__(16) float2 Xs[32 * 128];
    __shared__ __align__(16) float2 Ws[48 * 32];

    f2 acc[48];
    #pragma unroll
    for (int j = 0; j < 48; ++j) acc[j] = 0ULL;

    const float* xb = A.x[sel] + b * (Cc * Nn) + n0 + 2 * tid;

    for (int c0 = 0; c0 < Cc; c0 += 32) {
        #pragma unroll 8
        for (int c = 0; c < 32; ++c)
            Xs[c * 128 + tid] = *(const float2*)(xb + (c0 + c) * Nn);
        #pragma unroll
        for (int r = 0; r < 12; ++r) {
            int idx = tid + r * 128;
            int j = idx >> 5, k = idx & 31;
            const float* wsrc = (j < 16) ? (tw + (g*CGd + j)      * Cc)
                              : (j < 32) ? (pw + (g*CGd + (j-16)) * Cc)
                                         : (gw + (g*CGd + (j-32)) * Cc);
            float w = wsrc[c0 + k];
            Ws[j * 32 + k] = make_float2(w, w);
        }
        __syncthreads();
        #pragma unroll 2
        for (int k = 0; k < 32; k += 2) {
            f2 xv0 = *(const f2*)&Xs[k * 128 + tid];
            f2 xv1 = *(const f2*)&Xs[(k + 1) * 128 + tid];
            #pragma unroll
            for (int j = 0; j < 48; ++j) {
                F4 w = *(const F4*)&Ws[j * 32 + k];
                acc[j] = fma2(w.a, xv0, acc[j]);
                acc[j] = fma2(w.b, xv1, acc[j]);
            }
        }
        __syncthreads();
    }

    int bg = sb * Gg + g;
    int nq = n0 + 2 * tid;
    const float* tb = A.tb[sel]; const float* pb = A.pb[sel]; const float* gb = A.gb[sel];
    #pragma unroll
    for (int m = 0; m < 16; ++m) {
        float lo, hi;
        unpack2(acc[m], lo, hi);
        float bt = tb[g*CGd + m];
        *(float2*)(g_theta + (bg*CGd + m) * Nn + nq) =
            make_float2((lo + bt) * LOG2E, (hi + bt) * LOG2E);
        unpack2(acc[16 + m], lo, hi);
        float bp = pb[g*CGd + m];
        *(float2*)(g_phiT + (bg*CGd + m) * Nn + nq) = make_float2(lo + bp, hi + bp);
        unpack2(acc[32 + m], lo, hi);
        float bgg = gb[g*CGd + m];
        *(float2*)(g_gx + (bg*CGd + m) * Nn + nq) = make_float2(lo + bgg, hi + bgg);
    }
}

// ---------------- Kernel 2: fused attention, KEY-packed f32x2, 1 query/thread ----------------
// 128 threads = 128 queries per block; keys processed in packed pairs.
// Live regs ~160 -> no spills at 2 CTAs/SM.
__global__ __launch_bounds__(128, 2) void attn_kernel()
{
    int tid = threadIdx.x;
    int g   = blockIdx.y;
    int sb  = blockIdx.z;
    int bg  = sb * Gg + g;
    const float* th = g_theta + bg * CGd * Nn;
    const float* ks = g_phiT  + bg * CGd * Nn;
    const float* vs = g_gx    + bg * CGd * Nn;

    int nq = blockIdx.x * 128 + tid;

    f2 Q[16];
    #pragma unroll
    for (int d = 0; d < 16; ++d)
        Q[d] = dup2(th[d * Nn + nq]);     // pre-scaled by log2e

    f2 O[16];
    #pragma unroll
    for (int d = 0; d < 16; ++d) O[d] = 0ULL;
    f2 L = 0ULL;

    const f2 MAGIC  = dup2(12582912.0f);
    const f2 NMAGIC = dup2(-12582912.0f);
    const f2 NEG1   = dup2(-1.0f);
    const f2 C5 = dup2(1.3333558e-3f), C4 = dup2(9.6181291e-3f);
    const f2 C3 = dup2(5.5504109e-2f), C2 = dup2(2.4022651e-1f);
    const f2 C1 = dup2(6.9314718e-1f), C0 = dup2(1.0f);

    // [pair][d]: 16 f2 data + 2 f2 pad = 144B rows (16B aligned)
    __shared__ __align__(16) float2 KT[128 * 18];
    __shared__ __align__(16) float2 VT[128 * 18];

    for (int m0 = 0; m0 < Nn; m0 += 256) {
        #pragma unroll 4
        for (int d = 0; d < 16; ++d) {
            KT[tid * 18 + d] = *(const float2*)(ks + d * Nn + m0 + 2 * tid);
            VT[tid * 18 + d] = *(const float2*)(vs + d * Nn + m0 + 2 * tid);
        }
        __syncthreads();

        #pragma unroll 4
        for (int p = 0; p < 128; ++p) {
            const F4* Kp = (const F4*)(KT + p * 18);
            const F4* Vp = (const F4*)(VT + p * 18);
            F4 k0 = Kp[0], k1 = Kp[1], k2 = Kp[2], k3 = Kp[3];
            F4 k4 = Kp[4], k5 = Kp[5], k6 = Kp[6], k7 = Kp[7];

            // packed scores for key pair (2p, 2p+1)
            f2 s0 = mul2(Q[0], k0.a);  f2 s1 = mul2(Q[1], k0.b);
            s0 = fma2(Q[2],  k1.a, s0); s1 = fma2(Q[3],  k1.b, s1);
            s0 = fma2(Q[4],  k2.a, s0); s1 = fma2(Q[5],  k2.b, s1);
            s0 = fma2(Q[6],  k3.a, s0); s1 = fma2(Q[7],  k3.b, s1);
            s0 = fma2(Q[8],  k4.a, s0); s1 = fma2(Q[9],  k4.b, s1);
            s0 = fma2(Q[10], k5.a, s0); s1 = fma2(Q[11], k5.b, s1);
            s0 = fma2(Q[12], k6.a, s0); s1 = fma2(Q[13], k6.b, s1);
            s0 = fma2(Q[14], k7.a, s0); s1 = fma2(Q[15], k7.b, s1);
            f2 S = add2(s0, s1);

            // packed exp2 (scores already * log2e)
            f2 Z = add2(S, MAGIC);
            f2 F = fma2(add2(Z, NMAGIC), NEG1, S);
            f2 P = fma2(C5, F, C4);
            P = fma2(P, F, C3);
            P = fma2(P, F, C2);
            P = fma2(P, F, C1);
            P = fma2(P, F, C0);

            float zl, zh, pl, ph;
            unpack2(Z, zl, zh); unpack2(P, pl, ph);
            pl = __int_as_float(__float_as_int(pl) + ((__float_as_int(zl) - 0x4b400000) << 23));
            ph = __int_as_float(__float_as_int(ph) + ((__float_as_int(zh) - 0x4b400000) << 23));
            f2 PE = pack2(pl, ph);

            L = add2(L, PE);

            F4 v0 = Vp[0], v1 = Vp[1], v2 = Vp[2], v3 = Vp[3];
            O[0] = fma2(PE, v0.a, O[0]); O[1] = fma2(PE, v0.b, O[1]);
            O[2] = fma2(PE, v1.a, O[2]); O[3] = fma2(PE, v1.b, O[3]);
            O[4] = fma2(PE, v2.a, O[4]); O[5] = fma2(PE, v2.b, O[5]);
            O[6] = fma2(PE, v3.a, O[6]); O[7] = fma2(PE, v3.b, O[7]);
            F4 v4 = Vp[4], v5 = Vp[5], v6 = Vp[6], v7 = Vp[7];
            O[8]  = fma2(PE, v4.a, O[8]);  O[9]  = fma2(PE, v4.b, O[9]);
            O[10] = fma2(PE, v5.a, O[10]); O[11] = fma2(PE, v5.b, O[11]);
            O[12] = fma2(PE, v6.a, O[12]); O[13] = fma2(PE, v6.b, O[13]);
            O[14] = fma2(PE, v7.a, O[14]); O[15] = fma2(PE, v7.b, O[15]);
        }
        __syncthreads();
    }

    float ll, lh;
    unpack2(L, ll, lh);
    float inv = 1.0f / (ll + lh);
    int chan = sb * INTER + g * CGd;
    #pragma unroll
    for (int d = 0; d < 16; ++d) {
        float ol, oh; unpack2(O[d], ol, oh);
        g_outc[(chan + d) * Nn + nq] = (ol + oh) * inv;
    }
}

// ---------------- Kernel 3: W conv (GEMM) ----------------
struct WArgs { const float* Ww[2]; const float* Wb[2]; };

__global__ __launch_bounds__(128) void wconv_kernel(WArgs A)
{
    int tid = threadIdx.x;
    int n0  = blockIdx.x * 256;
    int o0  = blockIdx.y * 32;
    int sb  = blockIdx.z;
    int sel = sb >> 1;

    __shared__ __align__(16) float2 Xs[32 * 128];
    __shared__ __align__(16) float2 Ws[32 * 32];

    f2 acc[32];
    #pragma unroll
    for (int j = 0; j < 32; ++j) acc[j] = 0ULL;

    const float* src = g_outc + sb * (INTER * Nn) + n0 + 2 * tid;
    const float* Ww = A.Ww[sel];

    for (int i0 = 0; i0 < INTER; i0 += 32) {
        #pragma unroll 8
        for (int k = 0; k < 32; ++k)
            Xs[k * 128 + tid] = *(const float2*)(src + (i0 + k) * Nn);
        #pragma unroll
        for (int r = 0; r < 8; ++r) {
            int idx = tid + r * 128;
            int j = idx >> 5, k = idx & 31;
            float w = Ww[(o0 + j) * INTER + i0 + k];
            Ws[j * 32 + k] = make_float2(w, w);
        }
        __syncthreads();
        #pragma unroll 2
        for (int k = 0; k < 32; k += 2) {
            f2 xv0 = *(const f2*)&Xs[k * 128 + tid];
            f2 xv1 = *(const f2*)&Xs[(k + 1) * 128 + tid];
            #pragma unroll
            for (int j = 0; j < 32; ++j) {
                F4 w = *(const F4*)&Ws[j * 32 + k];
                acc[j] = fma2(w.a, xv0, acc[j]);
                acc[j] = fma2(w.b, xv1, acc[j]);
            }
        }
        __syncthreads();
    }

    float* dst = g_wy + sb * (Cc * Nn) + n0 + 2 * tid;
    const float* Wb = A.Wb[sel];
    #pragma unroll
    for (int j = 0; j < 32; ++j) {
        float lo, hi;
        unpack2(acc[j], lo, hi);
        float bb = Wb[o0 + j];
        *(float2*)(dst + (o0 + j) * Nn) = make_float2(lo + bb, hi + bb);
    }
}

// ---------------- Kernel 4: BN stats (float4 vectorized) ----------------
__global__ __launch_bounds__(256) void stats_kernel()
{
    int sel = blockIdx.x / Cc;
    int o   = blockIdx.x % Cc;
    int tid = threadIdx.x;
    const float4* r0 = (const float4*)(g_wy + ((sel*Bb + 0) * Cc + o) * Nn);
    const float4* r1 = (const float4*)(g_wy + ((sel*Bb + 1) * Cc + o) * Nn);

    float s = 0.f, s2 = 0.f;
    for (int i = tid; i < Nn/4; i += 256) {
        float4 a = r0[i], c = r1[i];
        s += a.x + a.y + a.z + a.w;
        s += c.x + c.y + c.z + c.w;
        s2 = fmaf(a.x, a.x, s2); s2 = fmaf(a.y, a.y, s2);
        s2 = fmaf(a.z, a.z, s2); s2 = fmaf(a.w, a.w, s2);
        s2 = fmaf(c.x, c.x, s2); s2 = fmaf(c.y, c.y, s2);
        s2 = fmaf(c.z, c.z, s2); s2 = fmaf(c.w, c.w, s2);
    }
    __shared__ float sh[256], sh2[256];
    sh[tid] = s; sh2[tid] = s2;
    __syncthreads();
    for (int st = 128; st > 0; st >>= 1) {
        if (tid < st) { sh[tid] += sh[tid + st]; sh2[tid] += sh2[tid + st]; }
        __syncthreads();
    }
    if (tid == 0) {
        float mean = sh[0] * (1.0f / (Bb * Nn));
        float var  = sh2[0] * (1.0f / (Bb * Nn)) - mean * mean;
        g_mean[blockIdx.x] = mean;
        g_rstd[blockIdx.x] = rsqrtf(var + EPSf);
    }
}

// ---------------- Kernel 5: BN apply + residual + ReLU (float4) ----------------
struct ApplyArgs {
    const float* x[2];
    const float* gam[2]; const float* bet[2];
};

__global__ __launch_bounds__(256) void apply_kernel(ApplyArgs A, float* __restrict__ out)
{
    int i4 = blockIdx.x * 256 + threadIdx.x;
    int idx = i4 * 4;
    int per = Bb * Cc * Nn;
    int sel = idx / per;
    int loc = idx - sel * per;
    int o   = (loc / Nn) % Cc;
    float m  = g_mean[sel*Cc + o];
    float rs = g_rstd[sel*Cc + o];
    float ga = A.gam[sel][o], be = A.bet[sel][o];
    float4 wv = *(const float4*)(g_wy + idx);
    float4 xv = *(const float4*)(A.x[sel] + loc);
    float4 r;
    r.x = fmaxf(fmaf((wv.x - m) * rs, ga, be) + xv.x, 0.f);
    r.y = fmaxf(fmaf((wv.y - m) * rs, ga, be) + xv.y, 0.f);
    r.z = fmaxf(fmaf((wv.z - m) * rs, ga, be) + xv.z, 0.f);
    r.w = fmaxf(fmaf((wv.w - m) * rs, ga, be) + xv.w, 0.f);
    *(float4*)(out + idx) = r;
}

// ---------------- launch ----------------
extern "C" void kernel_launch(void* const* d_in, const int* in_sizes, int n_in,
                              void* d_out, int out_size)
{
    ProjArgs P; WArgs W; ApplyArgs AP;
    for (int s = 0; s < 2; ++s) {
        P.x[s]  = (const float*)d_in[s];
        P.gw[s] = (const float*)d_in[2 + s*10 + 0];
        P.gb[s] = (const float*)d_in[2 + s*10 + 1];
        P.tw[s] = (const float*)d_in[2 + s*10 + 2];
        P.tb[s] = (const float*)d_in[2 + s*10 + 3];
        P.pw[s] = (const float*)d_in[2 + s*10 + 4];
        P.pb[s] = (const float*)d_in[2 + s*10 + 5];
        W.Ww[s] = (const float*)d_in[2 + s*10 + 6];
        W.Wb[s] = (const float*)d_in[2 + s*10 + 7];
        AP.x[s]   = (const float*)d_in[s];
        AP.gam[s] = (const float*)d_in[2 + s*10 + 8];
        AP.bet[s] = (const float*)d_in[2 + s*10 + 9];
    }

    proj_kernel <<<dim3(9, Gg, SEL*Bb), 128>>>(P);
    attn_kernel <<<dim3(18, Gg, SEL*Bb), 128>>>();
    wconv_kernel<<<dim3(9, Cc/32, SEL*Bb), 128>>>(W);
    stats_kernel<<<SEL*Cc, 256>>>();
    apply_kernel<<<(SEL*Bb*Cc*Nn)/1024, 256>>>(AP, (float*)d_out);
}